// round 13
// baseline (speedup 1.0000x reference)
#include <cuda_runtime.h>
#include <cuda_fp16.h>
#include <cstdint>
#include <math.h>

#define MAXN 100000
#define MAXE 1600000

// ---------------- scratch (device globals; no allocation allowed) ----------
// all feature rows stride-padded to 32B multiples (sector-aligned gathers)
__device__ __align__(16) __half g_t1[MAXN * 80];  // GEMM1 out (d=65, 160B)
__device__ __align__(16) __half g_h1[MAXN * 80];  // agg1 out  (d=65, 160B)
__device__ __align__(16) __half g_t2[MAXN * 64];  // GEMM2 out (d=50, 128B)
__device__ __align__(16) __half g_h2[MAXN * 64];  // agg2 out  (d=50, 128B)
__device__ __align__(16) __half g_a3[MAXN * 64];  // agg3 out  (d=50, 128B)
__device__ __align__(16) __half g_t3[MAXN * 80];  // GEMM3 out (d=65, 160B)
__device__ __align__(16) __half g_a4[MAXN * 80];  // agg4 out  (d=65, 160B)
__device__ __align__(16) __half g_wh[23040];      // packed fp16 weights
__device__ float g_dinv[MAXN];
__device__ int   g_cnt[MAXN];
__device__ int   g_fill[MAXN];
__device__ int   g_rowptr[MAXN + 1];
__device__ int   g_csr[MAXE];
__device__ int   g_bsum[128];

#define WOFF1 0
#define WOFF2 6912
#define WOFF3 11392
#define WOFF4 16000

// ---------------- CSR build ------------------------------------------------
__global__ void k_count(const int* __restrict__ dst, int E, int* __restrict__ cnt) {
    int e = blockIdx.x * blockDim.x + threadIdx.x;
    if (e < E) atomicAdd(&cnt[dst[e]], 1);
}

__global__ void k_dinv(const int* __restrict__ cnt, float* __restrict__ dinv, int n) {
    int i = blockIdx.x * blockDim.x + threadIdx.x;
    if (i < n) dinv[i] = rsqrtf((float)(cnt[i] + 1));   // +1 self loop
}

__global__ void k_scan_block(const int* __restrict__ cnt, int n,
                             int* __restrict__ incl, int* __restrict__ bsum) {
    __shared__ int sh[1024];
    int tid = threadIdx.x;
    int gid = blockIdx.x * 1024 + tid;
    int v = (gid < n) ? cnt[gid] : 0;
    sh[tid] = v;
    __syncthreads();
    for (int off = 1; off < 1024; off <<= 1) {
        int t = 0;
        if (tid >= off) t = sh[tid - off];
        __syncthreads();
        sh[tid] += t;
        __syncthreads();
    }
    if (gid < n) incl[gid] = sh[tid];
    if (tid == 1023) bsum[blockIdx.x] = sh[1023];
}

// scan the <=128 block sums (per block, in smem), add offset to rowptr,
// init fill cursor to the row START.
__global__ void k_finalize2(const int* __restrict__ bsum, int nb,
                            int* __restrict__ rowptr, const int* __restrict__ cnt,
                            int* __restrict__ fill, int n) {
    __shared__ int sh[128];
    int tid = threadIdx.x;
    if (tid < 128) sh[tid] = (tid < nb) ? bsum[tid] : 0;
    __syncthreads();
    if (tid == 0) {
        int acc = 0;
        for (int i = 0; i < nb; i++) { int v = sh[i]; sh[i] = acc; acc += v; }
    }
    __syncthreads();
    int i = blockIdx.x * blockDim.x + threadIdx.x;
    if (i < n) {
        int c = cnt[i];
        int r1 = rowptr[i + 1] + sh[i >> 10];
        rowptr[i + 1] = r1;
        fill[i] = r1 - c;                       // row start = cursor init
        if (i == 0) rowptr[0] = 0;
    }
}

__global__ void k_fill(const int* __restrict__ src, const int* __restrict__ dst, int E,
                       int* __restrict__ fill, int* __restrict__ csr) {
    int e = blockIdx.x * blockDim.x + threadIdx.x;
    if (e < E) {
        int p = atomicAdd(&fill[dst[e]], 1);
        csr[p] = src[e];
    }
}

// ---------------- weight conversion (fp32 -> fp16, zero-padded) ------------
__global__ void k_prep_w(const float* __restrict__ W1, const float* __restrict__ W2,
                         const float* __restrict__ W3, const float* __restrict__ W4,
                         __half* __restrict__ o) {
    int i = blockIdx.x * blockDim.x + threadIdx.x;
    if (i < 6912) {                                    // W1 [88x65] -> [96x72]
        int kk = i / 72;
        int nn = i - kk * 72;
        o[WOFF1 + i] = __float2half((kk < 88 && nn < 65) ? W1[kk * 65 + nn] : 0.f);
    } else if (i < 11392) {                            // W2 [65x50] -> [80x56]
        int j = i - 6912;
        int kk = j / 56;
        int nn = j - kk * 56;
        o[WOFF2 + j] = __float2half((kk < 65 && nn < 50) ? W2[kk * 50 + nn] : 0.f);
    } else if (i < 16000) {                            // W3 [50x65] -> [64x72]
        int j = i - 11392;
        int kk = j / 72;
        int nn = j - kk * 72;
        o[WOFF3 + j] = __float2half((kk < 50 && nn < 65) ? W3[kk * 65 + nn] : 0.f);
    } else if (i < 23040) {                            // W4 [65x88] -> [80x88]
        int j = i - 16000;
        int kk = j / 88;
        int nn = j - kk * 88;
        o[WOFF4 + j] = __float2half((kk < 65 && nn < 88) ? W4[kk * 88 + nn] : 0.f);
    }
}

// ---------------- tensor-core GEMM helpers ---------------------------------
__device__ __forceinline__ void ldsm_x4(unsigned int& a0, unsigned int& a1,
                                        unsigned int& a2, unsigned int& a3,
                                        const __half* p) {
    unsigned int addr = (unsigned int)__cvta_generic_to_shared((const void*)p);
    asm volatile("ldmatrix.sync.aligned.m8n8.x4.shared.b16 {%0,%1,%2,%3}, [%4];"
                 : "=r"(a0), "=r"(a1), "=r"(a2), "=r"(a3)
                 : "r"(addr));
}

__device__ __forceinline__ void ldsm_x2t(unsigned int& b0, unsigned int& b1,
                                         const __half* p) {
    unsigned int addr = (unsigned int)__cvta_generic_to_shared((const void*)p);
    asm volatile("ldmatrix.sync.aligned.m8n8.x2.trans.shared.b16 {%0,%1}, [%2];"
                 : "=r"(b0), "=r"(b1)
                 : "r"(addr));
}

__device__ __forceinline__ void mma16816(float& d0, float& d1, float& d2, float& d3,
                                         unsigned int a0, unsigned int a1,
                                         unsigned int a2, unsigned int a3,
                                         unsigned int b0, unsigned int b1) {
    asm volatile("mma.sync.aligned.m16n8k16.row.col.f32.f16.f16.f32 "
                 "{%0,%1,%2,%3}, {%4,%5,%6,%7}, {%8,%9}, {%0,%1,%2,%3};"
                 : "+f"(d0), "+f"(d1), "+f"(d2), "+f"(d3)
                 : "r"(a0), "r"(a1), "r"(a2), "r"(a3), "r"(b0), "r"(b1));
}

// C[N, Np] = A[N, Kp] * B[Kp, Np] (prepacked fp16 B). 128 rows, 256 threads.
// A-staging uses register prefetch (all LDGs independent -> high MLP).
template <int Kp, int Np, int AF32, int RELU, int SCALE, int OUT_HALF>
__global__ void __launch_bounds__(256)
k_gemm_tc(const void* Av,
          const __half* __restrict__ B,
          const float* __restrict__ bias,
          const float* __restrict__ dinv,
          void* Cv, int ldc, int M, int N) {
    const int KT = Kp / 16;
    const int NT = Np / 8;
    const int LDA = Kp + 8;
    const int LDB = Np;
    extern __shared__ char smem_raw[];
    __half* sA = (__half*)smem_raw;                 // 128 x LDA
    __half* sB = (__half*)smem_raw + 128 * LDA;     // Kp x LDB

    int tid = threadIdx.x;
    int warp = tid >> 5;
    int lane = tid & 31;
    int r0 = blockIdx.x * 128;

    if (AF32) {
        // 128 rows x 22 float4 = 2816 = 11 per thread; prefetch all 11
        const float4* Ag = (const float4*)Av;
        float4 f[11];
#pragma unroll
        for (int it = 0; it < 11; it++) {
            int i = tid + it * 256;
            int r = i / 22;
            int v = i - r * 22;
            int gr = r0 + r;
            f[it] = (gr < N) ? Ag[(size_t)gr * 22 + v]
                             : make_float4(0.f, 0.f, 0.f, 0.f);
        }
#pragma unroll
        for (int it = 0; it < 11; it++) {
            int i = tid + it * 256;
            int r = i / 22;
            int v = i - r * 22;
            __half2* p = (__half2*)&sA[r * LDA + v * 4];
            p[0] = __floats2half2_rn(f[it].x, f[it].y);
            p[1] = __floats2half2_rn(f[it].z, f[it].w);
        }
        for (int i = tid; i < 128 * 4; i += 256) {   // zero cols 88..95
            int r = i >> 2;
            int v = i & 3;
            *(__half2*)&sA[r * LDA + 88 + 2 * v] = __floats2half2_rn(0.f, 0.f);
        }
    } else {
        const int HV = Kp / 8;                       // uint4 per row (10 or 8)
        const int IT = HV / 2;                       // 128*HV/256
        const uint4* Ag = (const uint4*)Av;
        uint4 q[IT];
#pragma unroll
        for (int it = 0; it < IT; it++) {
            int i = tid + it * 256;
            int r = i / HV;
            int v = i - r * HV;
            int gr = r0 + r;
            q[it] = (gr < N) ? Ag[(size_t)gr * HV + v]
                             : make_uint4(0u, 0u, 0u, 0u);
        }
#pragma unroll
        for (int it = 0; it < IT; it++) {
            int i = tid + it * 256;
            int r = i / HV;
            int v = i - r * HV;
            *(uint4*)&sA[r * LDA + v * 8] = q[it];
        }
    }
    {
        const int BV = Np / 8;
        const uint4* Bg = (const uint4*)B;
        for (int i = tid; i < Kp * BV; i += 256) {
            int kk = i / BV;
            int v = i - kk * BV;
            *(uint4*)&sB[kk * LDB + v * 8] = Bg[i];
        }
    }
    __syncthreads();

    float acc[NT][4];
#pragma unroll
    for (int nt = 0; nt < NT; nt++) {
#pragma unroll
        for (int q2 = 0; q2 < 4; q2++) acc[nt][q2] = 0.f;
    }

#pragma unroll
    for (int kt = 0; kt < KT; kt++) {
        unsigned int a0, a1, a2, a3;
        const __half* pa = &sA[(warp * 16 + (lane & 15)) * LDA + kt * 16 + (lane >> 4) * 8];
        ldsm_x4(a0, a1, a2, a3, pa);
#pragma unroll
        for (int nt = 0; nt < NT; nt++) {
            unsigned int b0, b1;
            const __half* pb = &sB[(kt * 16 + (lane & 15)) * LDB + nt * 8];
            ldsm_x2t(b0, b1, pb);
            mma16816(acc[nt][0], acc[nt][1], acc[nt][2], acc[nt][3],
                     a0, a1, a2, a3, b0, b1);
        }
    }

    int row = r0 + warp * 16 + (lane >> 2);
    int colb = (lane & 3) * 2;
    float sc0 = 1.f;
    float sc1 = 1.f;
    if (SCALE) {
        sc0 = (row < N) ? dinv[row] : 0.f;
        sc1 = (row + 8 < N) ? dinv[row + 8] : 0.f;
    }
#pragma unroll
    for (int nt = 0; nt < NT; nt++) {
        int c0 = nt * 8 + colb;
        float b0v = 0.f;
        float b1v = 0.f;
        if (bias != nullptr) {
            b0v = (c0 < M) ? bias[c0] : 0.f;
            b1v = (c0 + 1 < M) ? bias[c0 + 1] : 0.f;
        }
        float v00 = acc[nt][0] + b0v;
        float v01 = acc[nt][1] + b1v;
        float v10 = acc[nt][2] + b0v;
        float v11 = acc[nt][3] + b1v;
        if (RELU) {
            v00 = fmaxf(v00, 0.f); v01 = fmaxf(v01, 0.f);
            v10 = fmaxf(v10, 0.f); v11 = fmaxf(v11, 0.f);
        }
        v00 *= sc0; v01 *= sc0; v10 *= sc1; v11 *= sc1;
        if (c0 >= M)     { v00 = 0.f; v10 = 0.f; }
        if (c0 + 1 >= M) { v01 = 0.f; v11 = 0.f; }
        if (OUT_HALF) {
            __half* C = (__half*)Cv;
            if (row < N)
                *(__half2*)&C[(size_t)row * ldc + c0] = __floats2half2_rn(v00, v01);
            if (row + 8 < N)
                *(__half2*)&C[(size_t)(row + 8) * ldc + c0] = __floats2half2_rn(v10, v11);
        } else {
            float* C = (float*)Cv;
            if (row < N)
                *(float2*)&C[(size_t)row * ldc + c0] = make_float2(v00, v01);
            if (row + 8 < N)
                *(float2*)&C[(size_t)(row + 8) * ldc + c0] = make_float2(v10, v11);
        }
    }
}

// ---------------- aggregation: SUBS edges / gather, 8-deep pipeline ---------
// uint4 (8-half) granularity, sector-aligned strides. Warp splits into SUBS
// sub-groups of 32/SUBS lanes; sub-group g gathers edge j+g; shfl reduce.
// Main loop keeps 8 independent gathers in flight (8*SUBS edges/iter).
__device__ __forceinline__ void add8(float* acc, uint4 q) {
    float2 f;
    f = __half22float2(*(__half2*)&q.x); acc[0] += f.x; acc[1] += f.y;
    f = __half22float2(*(__half2*)&q.y); acc[2] += f.x; acc[3] += f.y;
    f = __half22float2(*(__half2*)&q.z); acc[4] += f.x; acc[5] += f.y;
    f = __half22float2(*(__half2*)&q.w); acc[6] += f.x; acc[7] += f.y;
}

template <int LPE, int SUBS, int SIN, int SOUT, int D>
__global__ void k_agg(const uint4* __restrict__ t, uint4* __restrict__ o,
                      const int* __restrict__ rowptr, const int* __restrict__ csr,
                      const float* __restrict__ dinv,
                      const float* __restrict__ bias,
                      int relu, int post2, int N) {
    const int GRP = 32 / SUBS;          // lanes per sub-group
    int node = (blockIdx.x * blockDim.x + threadIdx.x) >> 5;
    int lane = threadIdx.x & 31;
    if (node >= N) return;
    int sub = lane / GRP;
    int ln = lane & (GRP - 1);
    bool act = ln < LPE;
    int beg = rowptr[node];
    int end = rowptr[node + 1];

    float acc[8];
#pragma unroll
    for (int k = 0; k < 8; k++) acc[k] = 0.f;
    const uint4 z4 = make_uint4(0u, 0u, 0u, 0u);

    int j = beg;
    // 8-deep pipeline: 8*SUBS edges per iteration
    for (; j + 8 * SUBS <= end; j += 8 * SUBS) {
        int s[8];
#pragma unroll
        for (int k = 0; k < 8; k++)
            s[k] = __ldg(&csr[j + k * SUBS + sub]);
        uint4 q[8];
#pragma unroll
        for (int k = 0; k < 8; k++)
            q[k] = act ? __ldg(&t[(size_t)s[k] * SIN + ln]) : z4;
#pragma unroll
        for (int k = 0; k < 8; k++)
            add8(acc, q[k]);
    }
    // 4-deep
    if (j + 4 * SUBS <= end) {
        int s[4];
#pragma unroll
        for (int k = 0; k < 4; k++)
            s[k] = __ldg(&csr[j + k * SUBS + sub]);
        uint4 q[4];
#pragma unroll
        for (int k = 0; k < 4; k++)
            q[k] = act ? __ldg(&t[(size_t)s[k] * SIN + ln]) : z4;
#pragma unroll
        for (int k = 0; k < 4; k++)
            add8(acc, q[k]);
        j += 4 * SUBS;
    }
    for (; j + SUBS <= end; j += SUBS) {
        int s0 = __ldg(&csr[j + sub]);
        uint4 q0 = act ? __ldg(&t[(size_t)s0 * SIN + ln]) : z4;
        add8(acc, q0);
    }
    if (j < end) {                        // leftover < SUBS edges
        int rem = end - j;
        uint4 q0 = z4;
        if (act && sub < rem) {
            int s0 = __ldg(&csr[j + sub]);
            q0 = __ldg(&t[(size_t)s0 * SIN + ln]);
        }
        add8(acc, q0);
    }
    // self loop (row already carries dinv_i): sub==0 only
    {
        uint4 q = (act && sub == 0) ? __ldg(&t[(size_t)node * SIN + ln]) : z4;
        add8(acc, q);
    }

    if (SUBS == 4) {
#pragma unroll
        for (int k = 0; k < 8; k++)
            acc[k] += __shfl_xor_sync(0xFFFFFFFFu, acc[k], 8);
    }
#pragma unroll
    for (int k = 0; k < 8; k++)
        acc[k] += __shfl_xor_sync(0xFFFFFFFFu, acc[k], 16);

    if (sub == 0 && ln < SOUT) {
        float di = dinv[node];
        uint4 w;
        __half2* wh2 = (__half2*)&w;
#pragma unroll
        for (int p = 0; p < 4; p++) {
            int c0 = 8 * ln + 2 * p;
            float v0 = acc[2 * p] * di;
            float v1 = acc[2 * p + 1] * di;
            if (bias != nullptr) {
                v0 += (c0 < D) ? bias[c0] : 0.f;
                v1 += (c0 + 1 < D) ? bias[c0 + 1] : 0.f;
            }
            if (relu) { v0 = fmaxf(v0, 0.f); v1 = fmaxf(v1, 0.f); }
            if (post2) { v0 *= di; v1 *= di; }
            if (c0 >= D) v0 = 0.f;
            if (c0 + 1 >= D) v1 = 0.f;
            wh2[p] = __floats2half2_rn(v0, v1);
        }
        o[(size_t)node * SOUT + ln] = w;
    }
}

// ---------------- launch ----------------------------------------------------
extern "C" void kernel_launch(void* const* d_in, const int* in_sizes, int n_in,
                              void* d_out, int out_size) {
    const float* x  = (const float*)d_in[0];
    const float* W1 = (const float*)d_in[1];
    const float* b1 = (const float*)d_in[2];
    const float* W2 = (const float*)d_in[3];
    const float* b2 = (const float*)d_in[4];
    const float* W3 = (const float*)d_in[5];
    const float* b3 = (const float*)d_in[6];
    const float* W4 = (const float*)d_in[7];
    const float* b4 = (const float*)d_in[8];
    const int*   ei = (const int*)d_in[9];

    int N = in_sizes[0] / 88;
    int E = in_sizes[9] / 2;
    const int* src = ei;
    const int* dst = ei + E;
    float* out = (float*)d_out;

    __half *t1, *h1, *t2, *h2, *a3, *t3, *a4, *wh;
    float* dinv;
    int *cnt, *fill, *rowptr, *csr, *bsum;
    cudaGetSymbolAddress((void**)&t1, g_t1);
    cudaGetSymbolAddress((void**)&h1, g_h1);
    cudaGetSymbolAddress((void**)&t2, g_t2);
    cudaGetSymbolAddress((void**)&h2, g_h2);
    cudaGetSymbolAddress((void**)&a3, g_a3);
    cudaGetSymbolAddress((void**)&t3, g_t3);
    cudaGetSymbolAddress((void**)&a4, g_a4);
    cudaGetSymbolAddress((void**)&wh, g_wh);
    cudaGetSymbolAddress((void**)&dinv, g_dinv);
    cudaGetSymbolAddress((void**)&cnt, g_cnt);
    cudaGetSymbolAddress((void**)&fill, g_fill);
    cudaGetSymbolAddress((void**)&rowptr, g_rowptr);
    cudaGetSymbolAddress((void**)&csr, g_csr);
    cudaGetSymbolAddress((void**)&bsum, g_bsum);

    int aggBlocks = (N * 32 + 255) / 256;
    int gemmBlocks = (N + 127) / 128;
    int nb = (N + 1023) / 1024;

    const int SM1 = (128 * 104 + 96 * 72) * 2;   // 40448
    const int SM2 = (128 * 88 + 80 * 56) * 2;    // 31488
    const int SM3 = (128 * 72 + 64 * 72) * 2;    // 27648
    const int SM4 = (128 * 88 + 80 * 88) * 2;    // 36608
    cudaFuncSetAttribute(k_gemm_tc<96, 72, 1, 0, 1, 1>,
                         cudaFuncAttributeMaxDynamicSharedMemorySize, SM1);
    cudaFuncSetAttribute(k_gemm_tc<80, 56, 0, 0, 1, 1>,
                         cudaFuncAttributeMaxDynamicSharedMemorySize, SM2);
    cudaFuncSetAttribute(k_gemm_tc<64, 72, 0, 1, 1, 1>,
                         cudaFuncAttributeMaxDynamicSharedMemorySize, SM3);
    cudaFuncSetAttribute(k_gemm_tc<80, 88, 0, 0, 0, 0>,
                         cudaFuncAttributeMaxDynamicSharedMemorySize, SM4);

    cudaMemsetAsync(cnt, 0, (size_t)N * sizeof(int));      // launch 1
    k_count<<<(E + 255) / 256, 256>>>(dst, E, cnt);        // launch 2
    k_dinv<<<(N + 255) / 256, 256>>>(cnt, dinv, N);        // launch 3
    k_prep_w<<<90, 256>>>(W1, W2, W3, W4, wh);             // launch 4
    // launch 5 <- profiled slot: L1 GEMM (register-prefetch staging)
    k_gemm_tc<96, 72, 1, 0, 1, 1><<<gemmBlocks, 256, SM1>>>(
        (const void*)x, wh + WOFF1, nullptr, dinv, (void*)t1, 80, 65, N);

    // CSR build
    k_scan_block<<<nb, 1024>>>(cnt, N, rowptr + 1, bsum);
    k_finalize2<<<(N + 255) / 256, 256>>>(bsum, nb, rowptr, cnt, fill, N);
    k_fill<<<(E + 255) / 256, 256>>>(src, dst, E, fill, csr);

    // L1 agg: h1 = relu(di*S(t1) + b1)
    k_agg<9, 2, 10, 10, 65><<<aggBlocks, 256>>>((const uint4*)t1, (uint4*)h1,
                                                rowptr, csr, dinv, b1, 1, 0, N);
    // L2: t2 = dinv o (h1@W2); h2 = dinv o (di*S(t2) + b2)
    k_gemm_tc<80, 56, 0, 0, 1, 1><<<gemmBlocks, 256, SM2>>>(
        (const void*)h1, wh + WOFF2, nullptr, dinv, (void*)t2, 64, 50, N);
    k_agg<7, 4, 8, 8, 50><<<aggBlocks, 256>>>((const uint4*)t2, (uint4*)h2,
                                              rowptr, csr, dinv, b2, 0, 1, N);
    // L3: a3 = di*S(h2); t3 = dinv o relu(a3@W3 + b3)
    k_agg<7, 4, 8, 8, 50><<<aggBlocks, 256>>>((const uint4*)h2, (uint4*)a3,
                                              rowptr, csr, dinv, nullptr, 0, 0, N);
    k_gemm_tc<64, 72, 0, 1, 1, 1><<<gemmBlocks, 256, SM3>>>(
        (const void*)a3, wh + WOFF3, b3, dinv, (void*)t3, 80, 65, N);
    // L4: a4 = di*S(t3); out = a4@W4 + b4
    k_agg<9, 2, 10, 10, 65><<<aggBlocks, 256>>>((const uint4*)t3, (uint4*)a4,
                                                rowptr, csr, dinv, nullptr, 0, 0, N);
    k_gemm_tc<80, 88, 0, 0, 0, 0><<<gemmBlocks, 256, SM4>>>(
        (const void*)a4, wh + WOFF4, b4, nullptr, (void*)out, 88, 88, N);
}

// round 14
// speedup vs baseline: 1.0718x; 1.0718x over previous
#include <cuda_runtime.h>
#include <cuda_fp16.h>
#include <cstdint>
#include <math.h>

#define MAXN 100000
#define MAXE 1600000

// ---------------- scratch (device globals; no allocation allowed) ----------
// all feature rows stride-padded to 32B multiples (sector-aligned gathers)
__device__ __align__(16) __half g_t1[MAXN * 80];  // GEMM1 out (d=65, 160B)
__device__ __align__(16) __half g_h1[MAXN * 80];  // agg1 out  (d=65, 160B)
__device__ __align__(16) __half g_t2[MAXN * 64];  // GEMM2 out (d=50, 128B)
__device__ __align__(16) __half g_h2[MAXN * 64];  // agg2 out  (d=50, 128B)
__device__ __align__(16) __half g_a3[MAXN * 64];  // agg3 out  (d=50, 128B)
__device__ __align__(16) __half g_t3[MAXN * 80];  // GEMM3 out (d=65, 160B)
__device__ __align__(16) __half g_a4[MAXN * 80];  // agg4 out  (d=65, 160B)
__device__ __align__(16) __half g_wh[23040];      // packed fp16 weights
__device__ float g_dinv[MAXN];
__device__ int   g_cnt[MAXN];
__device__ int   g_fill[MAXN];
__device__ int   g_rowptr[MAXN + 1];
__device__ int   g_csr[MAXE];
__device__ int   g_bsum[128];

#define WOFF1 0
#define WOFF2 6912
#define WOFF3 11392
#define WOFF4 16000

// ---------------- CSR build ------------------------------------------------
__global__ void k_count(const int* __restrict__ dst, int E, int* __restrict__ cnt) {
    int e = blockIdx.x * blockDim.x + threadIdx.x;
    if (e < E) atomicAdd(&cnt[dst[e]], 1);
}

// inclusive per-1024-block scan of cnt -> rowptr+1, block totals -> bsum.
// Also computes dinv (cnt is already in-register here).
__global__ void k_scan_block(const int* __restrict__ cnt, int n,
                             int* __restrict__ incl, int* __restrict__ bsum,
                             float* __restrict__ dinv) {
    __shared__ int sh[1024];
    int tid = threadIdx.x;
    int gid = blockIdx.x * 1024 + tid;
    int v = (gid < n) ? cnt[gid] : 0;
    if (gid < n) dinv[gid] = rsqrtf((float)(v + 1));   // +1 self loop
    sh[tid] = v;
    __syncthreads();
    for (int off = 1; off < 1024; off <<= 1) {
        int t = 0;
        if (tid >= off) t = sh[tid - off];
        __syncthreads();
        sh[tid] += t;
        __syncthreads();
    }
    if (gid < n) incl[gid] = sh[tid];
    if (tid == 1023) bsum[blockIdx.x] = sh[1023];
}

// scan the <=128 block sums (per block, in smem), add offset to rowptr,
// init fill cursor to the row START.
__global__ void k_finalize2(const int* __restrict__ bsum, int nb,
                            int* __restrict__ rowptr, const int* __restrict__ cnt,
                            int* __restrict__ fill, int n) {
    __shared__ int sh[128];
    int tid = threadIdx.x;
    if (tid < 128) sh[tid] = (tid < nb) ? bsum[tid] : 0;
    __syncthreads();
    if (tid == 0) {
        int acc = 0;
        for (int i = 0; i < nb; i++) { int v = sh[i]; sh[i] = acc; acc += v; }
    }
    __syncthreads();
    int i = blockIdx.x * blockDim.x + threadIdx.x;
    if (i < n) {
        int c = cnt[i];
        int r1 = rowptr[i + 1] + sh[i >> 10];
        rowptr[i + 1] = r1;
        fill[i] = r1 - c;                       // row start = cursor init
        if (i == 0) rowptr[0] = 0;
    }
}

__global__ void k_fill(const int* __restrict__ src, const int* __restrict__ dst, int E,
                       int* __restrict__ fill, int* __restrict__ csr) {
    int e = blockIdx.x * blockDim.x + threadIdx.x;
    if (e < E) {
        int p = atomicAdd(&fill[dst[e]], 1);
        csr[p] = src[e];
    }
}

// ---------------- weight conversion (fp32 -> fp16, zero-padded) ------------
__global__ void k_prep_w(const float* __restrict__ W1, const float* __restrict__ W2,
                         const float* __restrict__ W3, const float* __restrict__ W4,
                         __half* __restrict__ o) {
    int i = blockIdx.x * blockDim.x + threadIdx.x;
    if (i < 6912) {                                    // W1 [88x65] -> [96x72]
        int kk = i / 72;
        int nn = i - kk * 72;
        o[WOFF1 + i] = __float2half((kk < 88 && nn < 65) ? W1[kk * 65 + nn] : 0.f);
    } else if (i < 11392) {                            // W2 [65x50] -> [80x56]
        int j = i - 6912;
        int kk = j / 56;
        int nn = j - kk * 56;
        o[WOFF2 + j] = __float2half((kk < 65 && nn < 50) ? W2[kk * 50 + nn] : 0.f);
    } else if (i < 16000) {                            // W3 [50x65] -> [64x72]
        int j = i - 11392;
        int kk = j / 72;
        int nn = j - kk * 72;
        o[WOFF3 + j] = __float2half((kk < 50 && nn < 65) ? W3[kk * 65 + nn] : 0.f);
    } else if (i < 23040) {                            // W4 [65x88] -> [80x88]
        int j = i - 16000;
        int kk = j / 88;
        int nn = j - kk * 88;
        o[WOFF4 + j] = __float2half((kk < 65 && nn < 88) ? W4[kk * 88 + nn] : 0.f);
    }
}

// ---------------- tensor-core GEMM helpers ---------------------------------
__device__ __forceinline__ void ldsm_x4(unsigned int& a0, unsigned int& a1,
                                        unsigned int& a2, unsigned int& a3,
                                        const __half* p) {
    unsigned int addr = (unsigned int)__cvta_generic_to_shared((const void*)p);
    asm volatile("ldmatrix.sync.aligned.m8n8.x4.shared.b16 {%0,%1,%2,%3}, [%4];"
                 : "=r"(a0), "=r"(a1), "=r"(a2), "=r"(a3)
                 : "r"(addr));
}

__device__ __forceinline__ void ldsm_x2t(unsigned int& b0, unsigned int& b1,
                                         const __half* p) {
    unsigned int addr = (unsigned int)__cvta_generic_to_shared((const void*)p);
    asm volatile("ldmatrix.sync.aligned.m8n8.x2.trans.shared.b16 {%0,%1}, [%2];"
                 : "=r"(b0), "=r"(b1)
                 : "r"(addr));
}

__device__ __forceinline__ void mma16816(float& d0, float& d1, float& d2, float& d3,
                                         unsigned int a0, unsigned int a1,
                                         unsigned int a2, unsigned int a3,
                                         unsigned int b0, unsigned int b1) {
    asm volatile("mma.sync.aligned.m16n8k16.row.col.f32.f16.f16.f32 "
                 "{%0,%1,%2,%3}, {%4,%5,%6,%7}, {%8,%9}, {%0,%1,%2,%3};"
                 : "+f"(d0), "+f"(d1), "+f"(d2), "+f"(d3)
                 : "r"(a0), "r"(a1), "r"(a2), "r"(a3), "r"(b0), "r"(b1));
}

// C[N, Np] = A[N, Kp] * B[Kp, Np] (prepacked fp16 B). 128 rows, 256 threads.
// A-staging uses register prefetch (all LDGs independent -> high MLP).
template <int Kp, int Np, int AF32, int RELU, int SCALE, int OUT_HALF>
__global__ void __launch_bounds__(256)
k_gemm_tc(const void* Av,
          const __half* __restrict__ B,
          const float* __restrict__ bias,
          const float* __restrict__ dinv,
          void* Cv, int ldc, int M, int N) {
    const int KT = Kp / 16;
    const int NT = Np / 8;
    const int LDA = Kp + 8;
    const int LDB = Np;
    extern __shared__ char smem_raw[];
    __half* sA = (__half*)smem_raw;                 // 128 x LDA
    __half* sB = (__half*)smem_raw + 128 * LDA;     // Kp x LDB

    int tid = threadIdx.x;
    int warp = tid >> 5;
    int lane = tid & 31;
    int r0 = blockIdx.x * 128;

    if (AF32) {
        // 128 rows x 22 float4 = 2816 = 11 per thread; prefetch all 11
        const float4* Ag = (const float4*)Av;
        float4 f[11];
#pragma unroll
        for (int it = 0; it < 11; it++) {
            int i = tid + it * 256;
            int r = i / 22;
            int v = i - r * 22;
            int gr = r0 + r;
            f[it] = (gr < N) ? Ag[(size_t)gr * 22 + v]
                             : make_float4(0.f, 0.f, 0.f, 0.f);
        }
#pragma unroll
        for (int it = 0; it < 11; it++) {
            int i = tid + it * 256;
            int r = i / 22;
            int v = i - r * 22;
            __half2* p = (__half2*)&sA[r * LDA + v * 4];
            p[0] = __floats2half2_rn(f[it].x, f[it].y);
            p[1] = __floats2half2_rn(f[it].z, f[it].w);
        }
        for (int i = tid; i < 128 * 4; i += 256) {   // zero cols 88..95
            int r = i >> 2;
            int v = i & 3;
            *(__half2*)&sA[r * LDA + 88 + 2 * v] = __floats2half2_rn(0.f, 0.f);
        }
    } else {
        const int HV = Kp / 8;                       // uint4 per row (10 or 8)
        const int IT = HV / 2;                       // 128*HV/256
        const uint4* Ag = (const uint4*)Av;
        uint4 q[IT];
#pragma unroll
        for (int it = 0; it < IT; it++) {
            int i = tid + it * 256;
            int r = i / HV;
            int v = i - r * HV;
            int gr = r0 + r;
            q[it] = (gr < N) ? Ag[(size_t)gr * HV + v]
                             : make_uint4(0u, 0u, 0u, 0u);
        }
#pragma unroll
        for (int it = 0; it < IT; it++) {
            int i = tid + it * 256;
            int r = i / HV;
            int v = i - r * HV;
            *(uint4*)&sA[r * LDA + v * 8] = q[it];
        }
    }
    {
        const int BV = Np / 8;
        const uint4* Bg = (const uint4*)B;
        for (int i = tid; i < Kp * BV; i += 256) {
            int kk = i / BV;
            int v = i - kk * BV;
            *(uint4*)&sB[kk * LDB + v * 8] = Bg[i];
        }
    }
    __syncthreads();

    float acc[NT][4];
#pragma unroll
    for (int nt = 0; nt < NT; nt++) {
#pragma unroll
        for (int q2 = 0; q2 < 4; q2++) acc[nt][q2] = 0.f;
    }

#pragma unroll
    for (int kt = 0; kt < KT; kt++) {
        unsigned int a0, a1, a2, a3;
        const __half* pa = &sA[(warp * 16 + (lane & 15)) * LDA + kt * 16 + (lane >> 4) * 8];
        ldsm_x4(a0, a1, a2, a3, pa);
#pragma unroll
        for (int nt = 0; nt < NT; nt++) {
            unsigned int b0, b1;
            const __half* pb = &sB[(kt * 16 + (lane & 15)) * LDB + nt * 8];
            ldsm_x2t(b0, b1, pb);
            mma16816(acc[nt][0], acc[nt][1], acc[nt][2], acc[nt][3],
                     a0, a1, a2, a3, b0, b1);
        }
    }

    int row = r0 + warp * 16 + (lane >> 2);
    int colb = (lane & 3) * 2;
    float sc0 = 1.f;
    float sc1 = 1.f;
    if (SCALE) {
        sc0 = (row < N) ? dinv[row] : 0.f;
        sc1 = (row + 8 < N) ? dinv[row + 8] : 0.f;
    }
#pragma unroll
    for (int nt = 0; nt < NT; nt++) {
        int c0 = nt * 8 + colb;
        float b0v = 0.f;
        float b1v = 0.f;
        if (bias != nullptr) {
            b0v = (c0 < M) ? bias[c0] : 0.f;
            b1v = (c0 + 1 < M) ? bias[c0 + 1] : 0.f;
        }
        float v00 = acc[nt][0] + b0v;
        float v01 = acc[nt][1] + b1v;
        float v10 = acc[nt][2] + b0v;
        float v11 = acc[nt][3] + b1v;
        if (RELU) {
            v00 = fmaxf(v00, 0.f); v01 = fmaxf(v01, 0.f);
            v10 = fmaxf(v10, 0.f); v11 = fmaxf(v11, 0.f);
        }
        v00 *= sc0; v01 *= sc0; v10 *= sc1; v11 *= sc1;
        if (c0 >= M)     { v00 = 0.f; v10 = 0.f; }
        if (c0 + 1 >= M) { v01 = 0.f; v11 = 0.f; }
        if (OUT_HALF) {
            __half* C = (__half*)Cv;
            if (row < N)
                *(__half2*)&C[(size_t)row * ldc + c0] = __floats2half2_rn(v00, v01);
            if (row + 8 < N)
                *(__half2*)&C[(size_t)(row + 8) * ldc + c0] = __floats2half2_rn(v10, v11);
        } else {
            float* C = (float*)Cv;
            if (row < N)
                *(float2*)&C[(size_t)row * ldc + c0] = make_float2(v00, v01);
            if (row + 8 < N)
                *(float2*)&C[(size_t)(row + 8) * ldc + c0] = make_float2(v10, v11);
        }
    }
}

// ---------------- aggregation: SUBS edges / gather instruction --------------
// uint4 (8-half) granularity, sector-aligned strides. Warp splits into SUBS
// sub-groups of 32/SUBS lanes; sub-group g gathers edge j+g; shfl reduce.
// 4-deep pipeline (R12 best-known configuration).
__device__ __forceinline__ void add8(float* acc, uint4 q) {
    float2 f;
    f = __half22float2(*(__half2*)&q.x); acc[0] += f.x; acc[1] += f.y;
    f = __half22float2(*(__half2*)&q.y); acc[2] += f.x; acc[3] += f.y;
    f = __half22float2(*(__half2*)&q.z); acc[4] += f.x; acc[5] += f.y;
    f = __half22float2(*(__half2*)&q.w); acc[6] += f.x; acc[7] += f.y;
}

template <int LPE, int SUBS, int SIN, int SOUT, int D>
__global__ void k_agg(const uint4* __restrict__ t, uint4* __restrict__ o,
                      const int* __restrict__ rowptr, const int* __restrict__ csr,
                      const float* __restrict__ dinv,
                      const float* __restrict__ bias,
                      int relu, int post2, int N) {
    const int GRP = 32 / SUBS;          // lanes per sub-group
    int node = (blockIdx.x * blockDim.x + threadIdx.x) >> 5;
    int lane = threadIdx.x & 31;
    if (node >= N) return;
    int sub = lane / GRP;
    int ln = lane & (GRP - 1);
    bool act = ln < LPE;
    int beg = rowptr[node];
    int end = rowptr[node + 1];

    float acc[8];
#pragma unroll
    for (int k = 0; k < 8; k++) acc[k] = 0.f;
    const uint4 z4 = make_uint4(0u, 0u, 0u, 0u);

    int j = beg;
    for (; j + 4 * SUBS <= end; j += 4 * SUBS) {
        int s0 = __ldg(&csr[j + sub]);
        int s1 = __ldg(&csr[j + SUBS + sub]);
        int s2 = __ldg(&csr[j + 2 * SUBS + sub]);
        int s3 = __ldg(&csr[j + 3 * SUBS + sub]);
        uint4 q0 = act ? __ldg(&t[(size_t)s0 * SIN + ln]) : z4;
        uint4 q1 = act ? __ldg(&t[(size_t)s1 * SIN + ln]) : z4;
        uint4 q2 = act ? __ldg(&t[(size_t)s2 * SIN + ln]) : z4;
        uint4 q3 = act ? __ldg(&t[(size_t)s3 * SIN + ln]) : z4;
        add8(acc, q0); add8(acc, q1); add8(acc, q2); add8(acc, q3);
    }
    for (; j + SUBS <= end; j += SUBS) {
        int s0 = __ldg(&csr[j + sub]);
        uint4 q0 = act ? __ldg(&t[(size_t)s0 * SIN + ln]) : z4;
        add8(acc, q0);
    }
    if (j < end) {                        // leftover < SUBS edges
        int rem = end - j;
        uint4 q0 = z4;
        if (act && sub < rem) {
            int s0 = __ldg(&csr[j + sub]);
            q0 = __ldg(&t[(size_t)s0 * SIN + ln]);
        }
        add8(acc, q0);
    }
    // self loop (row already carries dinv_i): sub==0 only
    {
        uint4 q = (act && sub == 0) ? __ldg(&t[(size_t)node * SIN + ln]) : z4;
        add8(acc, q);
    }

    if (SUBS == 4) {
#pragma unroll
        for (int k = 0; k < 8; k++)
            acc[k] += __shfl_xor_sync(0xFFFFFFFFu, acc[k], 8);
    }
#pragma unroll
    for (int k = 0; k < 8; k++)
        acc[k] += __shfl_xor_sync(0xFFFFFFFFu, acc[k], 16);

    if (sub == 0 && ln < SOUT) {
        float di = dinv[node];
        uint4 w;
        __half2* wh2 = (__half2*)&w;
#pragma unroll
        for (int p = 0; p < 4; p++) {
            int c0 = 8 * ln + 2 * p;
            float v0 = acc[2 * p] * di;
            float v1 = acc[2 * p + 1] * di;
            if (bias != nullptr) {
                v0 += (c0 < D) ? bias[c0] : 0.f;
                v1 += (c0 + 1 < D) ? bias[c0 + 1] : 0.f;
            }
            if (relu) { v0 = fmaxf(v0, 0.f); v1 = fmaxf(v1, 0.f); }
            if (post2) { v0 *= di; v1 *= di; }
            if (c0 >= D) v0 = 0.f;
            if (c0 + 1 >= D) v1 = 0.f;
            wh2[p] = __floats2half2_rn(v0, v1);
        }
        o[(size_t)node * SOUT + ln] = w;
    }
}

// ---------------- launch ----------------------------------------------------
extern "C" void kernel_launch(void* const* d_in, const int* in_sizes, int n_in,
                              void* d_out, int out_size) {
    const float* x  = (const float*)d_in[0];
    const float* W1 = (const float*)d_in[1];
    const float* b1 = (const float*)d_in[2];
    const float* W2 = (const float*)d_in[3];
    const float* b2 = (const float*)d_in[4];
    const float* W3 = (const float*)d_in[5];
    const float* b3 = (const float*)d_in[6];
    const float* W4 = (const float*)d_in[7];
    const float* b4 = (const float*)d_in[8];
    const int*   ei = (const int*)d_in[9];

    int N = in_sizes[0] / 88;
    int E = in_sizes[9] / 2;
    const int* src = ei;
    const int* dst = ei + E;
    float* out = (float*)d_out;

    __half *t1, *h1, *t2, *h2, *a3, *t3, *a4, *wh;
    float* dinv;
    int *cnt, *fill, *rowptr, *csr, *bsum;
    cudaGetSymbolAddress((void**)&t1, g_t1);
    cudaGetSymbolAddress((void**)&h1, g_h1);
    cudaGetSymbolAddress((void**)&t2, g_t2);
    cudaGetSymbolAddress((void**)&h2, g_h2);
    cudaGetSymbolAddress((void**)&a3, g_a3);
    cudaGetSymbolAddress((void**)&t3, g_t3);
    cudaGetSymbolAddress((void**)&a4, g_a4);
    cudaGetSymbolAddress((void**)&wh, g_wh);
    cudaGetSymbolAddress((void**)&dinv, g_dinv);
    cudaGetSymbolAddress((void**)&cnt, g_cnt);
    cudaGetSymbolAddress((void**)&fill, g_fill);
    cudaGetSymbolAddress((void**)&rowptr, g_rowptr);
    cudaGetSymbolAddress((void**)&csr, g_csr);
    cudaGetSymbolAddress((void**)&bsum, g_bsum);

    int aggBlocks = (N * 32 + 255) / 256;
    int gemmBlocks = (N + 127) / 128;
    int nb = (N + 1023) / 1024;

    const int SM1 = (128 * 104 + 96 * 72) * 2;   // 40448
    const int SM2 = (128 * 88 + 80 * 56) * 2;    // 31488
    const int SM3 = (128 * 72 + 64 * 72) * 2;    // 27648
    const int SM4 = (128 * 88 + 80 * 88) * 2;    // 36608
    cudaFuncSetAttribute(k_gemm_tc<96, 72, 1, 0, 1, 1>,
                         cudaFuncAttributeMaxDynamicSharedMemorySize, SM1);
    cudaFuncSetAttribute(k_gemm_tc<80, 56, 0, 0, 1, 1>,
                         cudaFuncAttributeMaxDynamicSharedMemorySize, SM2);
    cudaFuncSetAttribute(k_gemm_tc<64, 72, 0, 1, 1, 1>,
                         cudaFuncAttributeMaxDynamicSharedMemorySize, SM3);
    cudaFuncSetAttribute(k_gemm_tc<80, 88, 0, 0, 0, 0>,
                         cudaFuncAttributeMaxDynamicSharedMemorySize, SM4);

    cudaMemsetAsync(cnt, 0, (size_t)N * sizeof(int));                 // launch 1
    k_count<<<(E + 255) / 256, 256>>>(dst, E, cnt);                   // launch 2
    k_scan_block<<<nb, 1024>>>(cnt, N, rowptr + 1, bsum, dinv);       // launch 3
    k_prep_w<<<90, 256>>>(W1, W2, W3, W4, wh);                        // launch 4
    // launch 5 <- profiled slot: L1 GEMM (register-prefetch staging)
    k_gemm_tc<96, 72, 1, 0, 1, 1><<<gemmBlocks, 256, SM1>>>(
        (const void*)x, wh + WOFF1, nullptr, dinv, (void*)t1, 80, 65, N);

    // CSR finalize + fill
    k_finalize2<<<(N + 255) / 256, 256>>>(bsum, nb, rowptr, cnt, fill, N);
    k_fill<<<(E + 255) / 256, 256>>>(src, dst, E, fill, csr);

    // L1 agg: h1 = relu(di*S(t1) + b1)
    k_agg<9, 2, 10, 10, 65><<<aggBlocks, 256>>>((const uint4*)t1, (uint4*)h1,
                                                rowptr, csr, dinv, b1, 1, 0, N);
    // L2: t2 = dinv o (h1@W2); h2 = dinv o (di*S(t2) + b2)
    k_gemm_tc<80, 56, 0, 0, 1, 1><<<gemmBlocks, 256, SM2>>>(
        (const void*)h1, wh + WOFF2, nullptr, dinv, (void*)t2, 64, 50, N);
    k_agg<7, 4, 8, 8, 50><<<aggBlocks, 256>>>((const uint4*)t2, (uint4*)h2,
                                              rowptr, csr, dinv, b2, 0, 1, N);
    // L3: a3 = di*S(h2); t3 = dinv o relu(a3@W3 + b3)
    k_agg<7, 4, 8, 8, 50><<<aggBlocks, 256>>>((const uint4*)h2, (uint4*)a3,
                                              rowptr, csr, dinv, nullptr, 0, 0, N);
    k_gemm_tc<64, 72, 0, 1, 1, 1><<<gemmBlocks, 256, SM3>>>(
        (const void*)a3, wh + WOFF3, b3, dinv, (void*)t3, 80, 65, N);
    // L4: a4 = di*S(t3); out = a4@W4 + b4
    k_agg<9, 2, 10, 10, 65><<<aggBlocks, 256>>>((const uint4*)t3, (uint4*)a4,
                                                rowptr, csr, dinv, nullptr, 0, 0, N);
    k_gemm_tc<80, 88, 0, 0, 0, 0><<<gemmBlocks, 256, SM4>>>(
        (const void*)a4, wh + WOFF4, b4, nullptr, (void*)out, 88, 88, N);
}

// round 15
// speedup vs baseline: 1.0719x; 1.0001x over previous
#include <cuda_runtime.h>
#include <cuda_fp16.h>
#include <cstdint>
#include <math.h>

#define MAXN 100000
#define MAXE 1600000

// ---------------- scratch (device globals; no allocation allowed) ----------
// all feature rows stride-padded to 32B multiples (sector-aligned gathers)
__device__ __align__(16) __half g_t1[MAXN * 80];  // GEMM1 out (d=65, 160B)
__device__ __align__(16) __half g_h1[MAXN * 80];  // agg1 out  (d=65, 160B)
__device__ __align__(16) __half g_t2[MAXN * 64];  // GEMM2 out (d=50, 128B)
__device__ __align__(16) __half g_h2[MAXN * 64];  // agg2 out  (d=50, 128B)
__device__ __align__(16) __half g_a3[MAXN * 64];  // agg3 out  (d=50, 128B)
__device__ __align__(16) __half g_t3[MAXN * 80];  // GEMM3 out (d=65, 160B)
__device__ __align__(16) __half g_a4[MAXN * 80];  // agg4 out  (d=65, 160B)
__device__ __align__(16) __half g_wh[23040];      // packed fp16 weights
__device__ float g_dinv[MAXN];
__device__ int   g_cnt[MAXN];
__device__ int   g_fill[MAXN];
__device__ int   g_rowptr[MAXN + 1];
__device__ int   g_csr[MAXE];
__device__ int   g_bsum[128];

#define WOFF1 0
#define WOFF2 6912
#define WOFF3 11392
#define WOFF4 16000

// ---------------- CSR build ------------------------------------------------
// 4 edges per thread, int4-vectorized loads, 4 independent atomic chains.
__global__ void k_count4(const int* __restrict__ dst, int E, int* __restrict__ cnt) {
    int t = blockIdx.x * blockDim.x + threadIdx.x;
    int e0 = t * 4;
    if (e0 + 4 <= E) {
        int4 d = *(const int4*)&dst[e0];
        atomicAdd(&cnt[d.x], 1);
        atomicAdd(&cnt[d.y], 1);
        atomicAdd(&cnt[d.z], 1);
        atomicAdd(&cnt[d.w], 1);
    } else {
        for (int e = e0; e < E; e++) atomicAdd(&cnt[dst[e]], 1);
    }
}

__global__ void k_fill4(const int* __restrict__ src, const int* __restrict__ dst, int E,
                        int* __restrict__ fill, int* __restrict__ csr) {
    int t = blockIdx.x * blockDim.x + threadIdx.x;
    int e0 = t * 4;
    if (e0 + 4 <= E) {
        int4 d = *(const int4*)&dst[e0];
        int4 s = *(const int4*)&src[e0];
        int p0 = atomicAdd(&fill[d.x], 1);
        int p1 = atomicAdd(&fill[d.y], 1);
        int p2 = atomicAdd(&fill[d.z], 1);
        int p3 = atomicAdd(&fill[d.w], 1);
        csr[p0] = s.x;
        csr[p1] = s.y;
        csr[p2] = s.z;
        csr[p3] = s.w;
    } else {
        for (int e = e0; e < E; e++) {
            int p = atomicAdd(&fill[dst[e]], 1);
            csr[p] = src[e];
        }
    }
}

// inclusive per-1024-block scan of cnt -> rowptr+1, block totals -> bsum.
// Also computes dinv (cnt is already in-register here).
__global__ void k_scan_block(const int* __restrict__ cnt, int n,
                             int* __restrict__ incl, int* __restrict__ bsum,
                             float* __restrict__ dinv) {
    __shared__ int sh[1024];
    int tid = threadIdx.x;
    int gid = blockIdx.x * 1024 + tid;
    int v = (gid < n) ? cnt[gid] : 0;
    if (gid < n) dinv[gid] = rsqrtf((float)(v + 1));   // +1 self loop
    sh[tid] = v;
    __syncthreads();
    for (int off = 1; off < 1024; off <<= 1) {
        int t = 0;
        if (tid >= off) t = sh[tid - off];
        __syncthreads();
        sh[tid] += t;
        __syncthreads();
    }
    if (gid < n) incl[gid] = sh[tid];
    if (tid == 1023) bsum[blockIdx.x] = sh[1023];
}

// scan the <=128 block sums (per block, in smem), add offset to rowptr,
// init fill cursor to the row START.
__global__ void k_finalize2(const int* __restrict__ bsum, int nb,
                            int* __restrict__ rowptr, const int* __restrict__ cnt,
                            int* __restrict__ fill, int n) {
    __shared__ int sh[128];
    int tid = threadIdx.x;
    if (tid < 128) sh[tid] = (tid < nb) ? bsum[tid] : 0;
    __syncthreads();
    if (tid == 0) {
        int acc = 0;
        for (int i = 0; i < nb; i++) { int v = sh[i]; sh[i] = acc; acc += v; }
    }
    __syncthreads();
    int i = blockIdx.x * blockDim.x + threadIdx.x;
    if (i < n) {
        int c = cnt[i];
        int r1 = rowptr[i + 1] + sh[i >> 10];
        rowptr[i + 1] = r1;
        fill[i] = r1 - c;                       // row start = cursor init
        if (i == 0) rowptr[0] = 0;
    }
}

// ---------------- weight conversion (fp32 -> fp16, zero-padded) ------------
__global__ void k_prep_w(const float* __restrict__ W1, const float* __restrict__ W2,
                         const float* __restrict__ W3, const float* __restrict__ W4,
                         __half* __restrict__ o) {
    int i = blockIdx.x * blockDim.x + threadIdx.x;
    if (i < 6912) {                                    // W1 [88x65] -> [96x72]
        int kk = i / 72;
        int nn = i - kk * 72;
        o[WOFF1 + i] = __float2half((kk < 88 && nn < 65) ? W1[kk * 65 + nn] : 0.f);
    } else if (i < 11392) {                            // W2 [65x50] -> [80x56]
        int j = i - 6912;
        int kk = j / 56;
        int nn = j - kk * 56;
        o[WOFF2 + j] = __float2half((kk < 65 && nn < 50) ? W2[kk * 50 + nn] : 0.f);
    } else if (i < 16000) {                            // W3 [50x65] -> [64x72]
        int j = i - 11392;
        int kk = j / 72;
        int nn = j - kk * 72;
        o[WOFF3 + j] = __float2half((kk < 50 && nn < 65) ? W3[kk * 65 + nn] : 0.f);
    } else if (i < 23040) {                            // W4 [65x88] -> [80x88]
        int j = i - 16000;
        int kk = j / 88;
        int nn = j - kk * 88;
        o[WOFF4 + j] = __float2half((kk < 65 && nn < 88) ? W4[kk * 88 + nn] : 0.f);
    }
}

// ---------------- tensor-core GEMM helpers ---------------------------------
__device__ __forceinline__ void ldsm_x4(unsigned int& a0, unsigned int& a1,
                                        unsigned int& a2, unsigned int& a3,
                                        const __half* p) {
    unsigned int addr = (unsigned int)__cvta_generic_to_shared((const void*)p);
    asm volatile("ldmatrix.sync.aligned.m8n8.x4.shared.b16 {%0,%1,%2,%3}, [%4];"
                 : "=r"(a0), "=r"(a1), "=r"(a2), "=r"(a3)
                 : "r"(addr));
}

__device__ __forceinline__ void ldsm_x2t(unsigned int& b0, unsigned int& b1,
                                         const __half* p) {
    unsigned int addr = (unsigned int)__cvta_generic_to_shared((const void*)p);
    asm volatile("ldmatrix.sync.aligned.m8n8.x2.trans.shared.b16 {%0,%1}, [%2];"
                 : "=r"(b0), "=r"(b1)
                 : "r"(addr));
}

__device__ __forceinline__ void mma16816(float& d0, float& d1, float& d2, float& d3,
                                         unsigned int a0, unsigned int a1,
                                         unsigned int a2, unsigned int a3,
                                         unsigned int b0, unsigned int b1) {
    asm volatile("mma.sync.aligned.m16n8k16.row.col.f32.f16.f16.f32 "
                 "{%0,%1,%2,%3}, {%4,%5,%6,%7}, {%8,%9}, {%0,%1,%2,%3};"
                 : "+f"(d0), "+f"(d1), "+f"(d2), "+f"(d3)
                 : "r"(a0), "r"(a1), "r"(a2), "r"(a3), "r"(b0), "r"(b1));
}

// C[N, Np] = A[N, Kp] * B[Kp, Np] (prepacked fp16 B). 128 rows, 256 threads.
// A-staging uses register prefetch (all LDGs independent -> high MLP).
template <int Kp, int Np, int AF32, int RELU, int SCALE, int OUT_HALF>
__global__ void __launch_bounds__(256)
k_gemm_tc(const void* Av,
          const __half* __restrict__ B,
          const float* __restrict__ bias,
          const float* __restrict__ dinv,
          void* Cv, int ldc, int M, int N) {
    const int KT = Kp / 16;
    const int NT = Np / 8;
    const int LDA = Kp + 8;
    const int LDB = Np;
    extern __shared__ char smem_raw[];
    __half* sA = (__half*)smem_raw;                 // 128 x LDA
    __half* sB = (__half*)smem_raw + 128 * LDA;     // Kp x LDB

    int tid = threadIdx.x;
    int warp = tid >> 5;
    int lane = tid & 31;
    int r0 = blockIdx.x * 128;

    if (AF32) {
        // 128 rows x 22 float4 = 2816 = 11 per thread; prefetch all 11
        const float4* Ag = (const float4*)Av;
        float4 f[11];
#pragma unroll
        for (int it = 0; it < 11; it++) {
            int i = tid + it * 256;
            int r = i / 22;
            int v = i - r * 22;
            int gr = r0 + r;
            f[it] = (gr < N) ? Ag[(size_t)gr * 22 + v]
                             : make_float4(0.f, 0.f, 0.f, 0.f);
        }
#pragma unroll
        for (int it = 0; it < 11; it++) {
            int i = tid + it * 256;
            int r = i / 22;
            int v = i - r * 22;
            __half2* p = (__half2*)&sA[r * LDA + v * 4];
            p[0] = __floats2half2_rn(f[it].x, f[it].y);
            p[1] = __floats2half2_rn(f[it].z, f[it].w);
        }
        for (int i = tid; i < 128 * 4; i += 256) {   // zero cols 88..95
            int r = i >> 2;
            int v = i & 3;
            *(__half2*)&sA[r * LDA + 88 + 2 * v] = __floats2half2_rn(0.f, 0.f);
        }
    } else {
        const int HV = Kp / 8;                       // uint4 per row (10 or 8)
        const int IT = HV / 2;                       // 128*HV/256
        const uint4* Ag = (const uint4*)Av;
        uint4 q[IT];
#pragma unroll
        for (int it = 0; it < IT; it++) {
            int i = tid + it * 256;
            int r = i / HV;
            int v = i - r * HV;
            int gr = r0 + r;
            q[it] = (gr < N) ? Ag[(size_t)gr * HV + v]
                             : make_uint4(0u, 0u, 0u, 0u);
        }
#pragma unroll
        for (int it = 0; it < IT; it++) {
            int i = tid + it * 256;
            int r = i / HV;
            int v = i - r * HV;
            *(uint4*)&sA[r * LDA + v * 8] = q[it];
        }
    }
    {
        const int BV = Np / 8;
        const uint4* Bg = (const uint4*)B;
        for (int i = tid; i < Kp * BV; i += 256) {
            int kk = i / BV;
            int v = i - kk * BV;
            *(uint4*)&sB[kk * LDB + v * 8] = Bg[i];
        }
    }
    __syncthreads();

    float acc[NT][4];
#pragma unroll
    for (int nt = 0; nt < NT; nt++) {
#pragma unroll
        for (int q2 = 0; q2 < 4; q2++) acc[nt][q2] = 0.f;
    }

#pragma unroll
    for (int kt = 0; kt < KT; kt++) {
        unsigned int a0, a1, a2, a3;
        const __half* pa = &sA[(warp * 16 + (lane & 15)) * LDA + kt * 16 + (lane >> 4) * 8];
        ldsm_x4(a0, a1, a2, a3, pa);
#pragma unroll
        for (int nt = 0; nt < NT; nt++) {
            unsigned int b0, b1;
            const __half* pb = &sB[(kt * 16 + (lane & 15)) * LDB + nt * 8];
            ldsm_x2t(b0, b1, pb);
            mma16816(acc[nt][0], acc[nt][1], acc[nt][2], acc[nt][3],
                     a0, a1, a2, a3, b0, b1);
        }
    }

    int row = r0 + warp * 16 + (lane >> 2);
    int colb = (lane & 3) * 2;
    float sc0 = 1.f;
    float sc1 = 1.f;
    if (SCALE) {
        sc0 = (row < N) ? dinv[row] : 0.f;
        sc1 = (row + 8 < N) ? dinv[row + 8] : 0.f;
    }
#pragma unroll
    for (int nt = 0; nt < NT; nt++) {
        int c0 = nt * 8 + colb;
        float b0v = 0.f;
        float b1v = 0.f;
        if (bias != nullptr) {
            b0v = (c0 < M) ? bias[c0] : 0.f;
            b1v = (c0 + 1 < M) ? bias[c0 + 1] : 0.f;
        }
        float v00 = acc[nt][0] + b0v;
        float v01 = acc[nt][1] + b1v;
        float v10 = acc[nt][2] + b0v;
        float v11 = acc[nt][3] + b1v;
        if (RELU) {
            v00 = fmaxf(v00, 0.f); v01 = fmaxf(v01, 0.f);
            v10 = fmaxf(v10, 0.f); v11 = fmaxf(v11, 0.f);
        }
        v00 *= sc0; v01 *= sc0; v10 *= sc1; v11 *= sc1;
        if (c0 >= M)     { v00 = 0.f; v10 = 0.f; }
        if (c0 + 1 >= M) { v01 = 0.f; v11 = 0.f; }
        if (OUT_HALF) {
            __half* C = (__half*)Cv;
            if (row < N)
                *(__half2*)&C[(size_t)row * ldc + c0] = __floats2half2_rn(v00, v01);
            if (row + 8 < N)
                *(__half2*)&C[(size_t)(row + 8) * ldc + c0] = __floats2half2_rn(v10, v11);
        } else {
            float* C = (float*)Cv;
            if (row < N)
                *(float2*)&C[(size_t)row * ldc + c0] = make_float2(v00, v01);
            if (row + 8 < N)
                *(float2*)&C[(size_t)(row + 8) * ldc + c0] = make_float2(v10, v11);
        }
    }
}

// ---------------- aggregation: SUBS edges / gather instruction --------------
// uint4 (8-half) granularity, sector-aligned strides. Warp splits into SUBS
// sub-groups of 32/SUBS lanes; sub-group g gathers edge j+g; shfl reduce.
// 4-deep pipeline (best-known configuration).
__device__ __forceinline__ void add8(float* acc, uint4 q) {
    float2 f;
    f = __half22float2(*(__half2*)&q.x); acc[0] += f.x; acc[1] += f.y;
    f = __half22float2(*(__half2*)&q.y); acc[2] += f.x; acc[3] += f.y;
    f = __half22float2(*(__half2*)&q.z); acc[4] += f.x; acc[5] += f.y;
    f = __half22float2(*(__half2*)&q.w); acc[6] += f.x; acc[7] += f.y;
}

template <int LPE, int SUBS, int SIN, int SOUT, int D>
__global__ void k_agg(const uint4* __restrict__ t, uint4* __restrict__ o,
                      const int* __restrict__ rowptr, const int* __restrict__ csr,
                      const float* __restrict__ dinv,
                      const float* __restrict__ bias,
                      int relu, int post2, int N) {
    const int GRP = 32 / SUBS;          // lanes per sub-group
    int node = (blockIdx.x * blockDim.x + threadIdx.x) >> 5;
    int lane = threadIdx.x & 31;
    if (node >= N) return;
    int sub = lane / GRP;
    int ln = lane & (GRP - 1);
    bool act = ln < LPE;
    int beg = rowptr[node];
    int end = rowptr[node + 1];

    float acc[8];
#pragma unroll
    for (int k = 0; k < 8; k++) acc[k] = 0.f;
    const uint4 z4 = make_uint4(0u, 0u, 0u, 0u);

    int j = beg;
    for (; j + 4 * SUBS <= end; j += 4 * SUBS) {
        int s0 = __ldg(&csr[j + sub]);
        int s1 = __ldg(&csr[j + SUBS + sub]);
        int s2 = __ldg(&csr[j + 2 * SUBS + sub]);
        int s3 = __ldg(&csr[j + 3 * SUBS + sub]);
        uint4 q0 = act ? __ldg(&t[(size_t)s0 * SIN + ln]) : z4;
        uint4 q1 = act ? __ldg(&t[(size_t)s1 * SIN + ln]) : z4;
        uint4 q2 = act ? __ldg(&t[(size_t)s2 * SIN + ln]) : z4;
        uint4 q3 = act ? __ldg(&t[(size_t)s3 * SIN + ln]) : z4;
        add8(acc, q0); add8(acc, q1); add8(acc, q2); add8(acc, q3);
    }
    for (; j + SUBS <= end; j += SUBS) {
        int s0 = __ldg(&csr[j + sub]);
        uint4 q0 = act ? __ldg(&t[(size_t)s0 * SIN + ln]) : z4;
        add8(acc, q0);
    }
    if (j < end) {                        // leftover < SUBS edges
        int rem = end - j;
        uint4 q0 = z4;
        if (act && sub < rem) {
            int s0 = __ldg(&csr[j + sub]);
            q0 = __ldg(&t[(size_t)s0 * SIN + ln]);
        }
        add8(acc, q0);
    }
    // self loop (row already carries dinv_i): sub==0 only
    {
        uint4 q = (act && sub == 0) ? __ldg(&t[(size_t)node * SIN + ln]) : z4;
        add8(acc, q);
    }

    if (SUBS == 4) {
#pragma unroll
        for (int k = 0; k < 8; k++)
            acc[k] += __shfl_xor_sync(0xFFFFFFFFu, acc[k], 8);
    }
#pragma unroll
    for (int k = 0; k < 8; k++)
        acc[k] += __shfl_xor_sync(0xFFFFFFFFu, acc[k], 16);

    if (sub == 0 && ln < SOUT) {
        float di = dinv[node];
        uint4 w;
        __half2* wh2 = (__half2*)&w;
#pragma unroll
        for (int p = 0; p < 4; p++) {
            int c0 = 8 * ln + 2 * p;
            float v0 = acc[2 * p] * di;
            float v1 = acc[2 * p + 1] * di;
            if (bias != nullptr) {
                v0 += (c0 < D) ? bias[c0] : 0.f;
                v1 += (c0 + 1 < D) ? bias[c0 + 1] : 0.f;
            }
            if (relu) { v0 = fmaxf(v0, 0.f); v1 = fmaxf(v1, 0.f); }
            if (post2) { v0 *= di; v1 *= di; }
            if (c0 >= D) v0 = 0.f;
            if (c0 + 1 >= D) v1 = 0.f;
            wh2[p] = __floats2half2_rn(v0, v1);
        }
        o[(size_t)node * SOUT + ln] = w;
    }
}

// ---------------- launch ----------------------------------------------------
extern "C" void kernel_launch(void* const* d_in, const int* in_sizes, int n_in,
                              void* d_out, int out_size) {
    const float* x  = (const float*)d_in[0];
    const float* W1 = (const float*)d_in[1];
    const float* b1 = (const float*)d_in[2];
    const float* W2 = (const float*)d_in[3];
    const float* b2 = (const float*)d_in[4];
    const float* W3 = (const float*)d_in[5];
    const float* b3 = (const float*)d_in[6];
    const float* W4 = (const float*)d_in[7];
    const float* b4 = (const float*)d_in[8];
    const int*   ei = (const int*)d_in[9];

    int N = in_sizes[0] / 88;
    int E = in_sizes[9] / 2;
    const int* src = ei;
    const int* dst = ei + E;
    float* out = (float*)d_out;

    __half *t1, *h1, *t2, *h2, *a3, *t3, *a4, *wh;
    float* dinv;
    int *cnt, *fill, *rowptr, *csr, *bsum;
    cudaGetSymbolAddress((void**)&t1, g_t1);
    cudaGetSymbolAddress((void**)&h1, g_h1);
    cudaGetSymbolAddress((void**)&t2, g_t2);
    cudaGetSymbolAddress((void**)&h2, g_h2);
    cudaGetSymbolAddress((void**)&a3, g_a3);
    cudaGetSymbolAddress((void**)&t3, g_t3);
    cudaGetSymbolAddress((void**)&a4, g_a4);
    cudaGetSymbolAddress((void**)&wh, g_wh);
    cudaGetSymbolAddress((void**)&dinv, g_dinv);
    cudaGetSymbolAddress((void**)&cnt, g_cnt);
    cudaGetSymbolAddress((void**)&fill, g_fill);
    cudaGetSymbolAddress((void**)&rowptr, g_rowptr);
    cudaGetSymbolAddress((void**)&csr, g_csr);
    cudaGetSymbolAddress((void**)&bsum, g_bsum);

    int aggBlocks = (N * 32 + 255) / 256;
    int gemmBlocks = (N + 127) / 128;
    int nb = (N + 1023) / 1024;
    int e4Blocks = ((E + 3) / 4 + 255) / 256;

    const int SM1 = (128 * 104 + 96 * 72) * 2;   // 40448
    const int SM2 = (128 * 88 + 80 * 56) * 2;    // 31488
    const int SM3 = (128 * 72 + 64 * 72) * 2;    // 27648
    const int SM4 = (128 * 88 + 80 * 88) * 2;    // 36608
    cudaFuncSetAttribute(k_gemm_tc<96, 72, 1, 0, 1, 1>,
                         cudaFuncAttributeMaxDynamicSharedMemorySize, SM1);
    cudaFuncSetAttribute(k_gemm_tc<80, 56, 0, 0, 1, 1>,
                         cudaFuncAttributeMaxDynamicSharedMemorySize, SM2);
    cudaFuncSetAttribute(k_gemm_tc<64, 72, 0, 1, 1, 1>,
                         cudaFuncAttributeMaxDynamicSharedMemorySize, SM3);
    cudaFuncSetAttribute(k_gemm_tc<80, 88, 0, 0, 0, 0>,
                         cudaFuncAttributeMaxDynamicSharedMemorySize, SM4);

    cudaMemsetAsync(cnt, 0, (size_t)N * sizeof(int));                 // (memset)
    k_count4<<<e4Blocks, 256>>>(dst, E, cnt);                         // launch 1
    k_scan_block<<<nb, 1024>>>(cnt, N, rowptr + 1, bsum, dinv);       // launch 2
    k_finalize2<<<(N + 255) / 256, 256>>>(bsum, nb, rowptr, cnt, fill, N); // 3
    // launch 4 <- profiled slot: MLP-4 CSR fill
    k_fill4<<<e4Blocks, 256>>>(src, dst, E, fill, csr);

    k_prep_w<<<90, 256>>>(W1, W2, W3, W4, wh);                        // launch 5
    // L1: t1 = dinv o (x@W1)
    k_gemm_tc<96, 72, 1, 0, 1, 1><<<gemmBlocks, 256, SM1>>>(
        (const void*)x, wh + WOFF1, nullptr, dinv, (void*)t1, 80, 65, N);

    // L1 agg: h1 = relu(di*S(t1) + b1)
    k_agg<9, 2, 10, 10, 65><<<aggBlocks, 256>>>((const uint4*)t1, (uint4*)h1,
                                                rowptr, csr, dinv, b1, 1, 0, N);
    // L2: t2 = dinv o (h1@W2); h2 = dinv o (di*S(t2) + b2)
    k_gemm_tc<80, 56, 0, 0, 1, 1><<<gemmBlocks, 256, SM2>>>(
        (const void*)h1, wh + WOFF2, nullptr, dinv, (void*)t2, 64, 50, N);
    k_agg<7, 4, 8, 8, 50><<<aggBlocks, 256>>>((const uint4*)t2, (uint4*)h2,
                                              rowptr, csr, dinv, b2, 0, 1, N);
    // L3: a3 = di*S(h2); t3 = dinv o relu(a3@W3 + b3)
    k_agg<7, 4, 8, 8, 50><<<aggBlocks, 256>>>((const uint4*)h2, (uint4*)a3,
                                              rowptr, csr, dinv, nullptr, 0, 0, N);
    k_gemm_tc<64, 72, 0, 1, 1, 1><<<gemmBlocks, 256, SM3>>>(
        (const void*)a3, wh + WOFF3, b3, dinv, (void*)t3, 80, 65, N);
    // L4: a4 = di*S(t3); out = a4@W4 + b4
    k_agg<9, 2, 10, 10, 65><<<aggBlocks, 256>>>((const uint4*)t3, (uint4*)a4,
                                                rowptr, csr, dinv, nullptr, 0, 0, N);
    k_gemm_tc<80, 88, 0, 0, 0, 0><<<gemmBlocks, 256, SM4>>>(
        (const void*)a4, wh + WOFF4, b4, nullptr, (void*)out, 88, 88, N);
}

// round 16
// speedup vs baseline: 1.0822x; 1.0096x over previous
#include <cuda_runtime.h>
#include <cuda_fp16.h>
#include <cstdint>
#include <math.h>

#define MAXN 100000
#define MAXE 1600000

// ---------------- scratch (device globals; no allocation allowed) ----------
// all feature rows stride-padded to 32B multiples (sector-aligned gathers)
__device__ __align__(16) __half g_t1[MAXN * 80];  // GEMM1 out (d=65, 160B)
__device__ __align__(16) __half g_h1[MAXN * 80];  // agg1 out  (d=65, 160B)
__device__ __align__(16) __half g_t2[MAXN * 64];  // GEMM2 out (d=50, 128B)
__device__ __align__(16) __half g_h2[MAXN * 64];  // agg2 out  (d=50, 128B)
__device__ __align__(16) __half g_a3[MAXN * 64];  // agg3 out  (d=50, 128B)
__device__ __align__(16) __half g_t3[MAXN * 80];  // GEMM3 out (d=65, 160B)
__device__ __align__(16) __half g_a4[MAXN * 80];  // agg4 out  (d=65, 160B)
__device__ __align__(16) __half g_wh[23040];      // packed fp16 weights
__device__ float g_dinv[MAXN];
__device__ int   g_cnt[MAXN];
__device__ int   g_slot[MAXE];                     // per-edge within-row slot
__device__ int   g_rowptr[MAXN + 1];
__device__ int   g_csr[MAXE];
__device__ int   g_bsum[128];

#define WOFF1 0
#define WOFF2 6912
#define WOFF3 11392
#define WOFF4 16000

// ---------------- CSR build ------------------------------------------------
// count records the atomic's return value = the edge's slot within its row.
__global__ void k_count4(const int* __restrict__ dst, int E,
                         int* __restrict__ cnt, int* __restrict__ slot) {
    int t = blockIdx.x * blockDim.x + threadIdx.x;
    int e0 = t * 4;
    if (e0 + 4 <= E) {
        int4 d = *(const int4*)&dst[e0];
        int4 p;
        p.x = atomicAdd(&cnt[d.x], 1);
        p.y = atomicAdd(&cnt[d.y], 1);
        p.z = atomicAdd(&cnt[d.z], 1);
        p.w = atomicAdd(&cnt[d.w], 1);
        *(int4*)&slot[e0] = p;
    } else {
        for (int e = e0; e < E; e++) slot[e] = atomicAdd(&cnt[dst[e]], 1);
    }
}

// atomic-free fill: csr[rowptr[dst] + slot] = src  (pure loads + scatter)
__global__ void k_fill4(const int* __restrict__ src, const int* __restrict__ dst, int E,
                        const int* __restrict__ rowptr, const int* __restrict__ slot,
                        int* __restrict__ csr) {
    int t = blockIdx.x * blockDim.x + threadIdx.x;
    int e0 = t * 4;
    if (e0 + 4 <= E) {
        int4 d = *(const int4*)&dst[e0];
        int4 s = *(const int4*)&src[e0];
        int4 sl = *(const int4*)&slot[e0];
        int r0 = __ldg(&rowptr[d.x]);
        int r1 = __ldg(&rowptr[d.y]);
        int r2 = __ldg(&rowptr[d.z]);
        int r3 = __ldg(&rowptr[d.w]);
        csr[r0 + sl.x] = s.x;
        csr[r1 + sl.y] = s.y;
        csr[r2 + sl.z] = s.z;
        csr[r3 + sl.w] = s.w;
    } else {
        for (int e = e0; e < E; e++)
            csr[__ldg(&rowptr[dst[e]]) + slot[e]] = src[e];
    }
}

// inclusive per-1024-block scan of cnt -> rowptr+1, block totals -> bsum.
// Also computes dinv (cnt is already in-register here).
__global__ void k_scan_block(const int* __restrict__ cnt, int n,
                             int* __restrict__ incl, int* __restrict__ bsum,
                             float* __restrict__ dinv) {
    __shared__ int sh[1024];
    int tid = threadIdx.x;
    int gid = blockIdx.x * 1024 + tid;
    int v = (gid < n) ? cnt[gid] : 0;
    if (gid < n) dinv[gid] = rsqrtf((float)(v + 1));   // +1 self loop
    sh[tid] = v;
    __syncthreads();
    for (int off = 1; off < 1024; off <<= 1) {
        int t = 0;
        if (tid >= off) t = sh[tid - off];
        __syncthreads();
        sh[tid] += t;
        __syncthreads();
    }
    if (gid < n) incl[gid] = sh[tid];
    if (tid == 1023) bsum[blockIdx.x] = sh[1023];
}

// scan the <=128 block sums (per block, in smem), add offset to rowptr.
__global__ void k_finalize2(const int* __restrict__ bsum, int nb,
                            int* __restrict__ rowptr, int n) {
    __shared__ int sh[128];
    int tid = threadIdx.x;
    if (tid < 128) sh[tid] = (tid < nb) ? bsum[tid] : 0;
    __syncthreads();
    if (tid == 0) {
        int acc = 0;
        for (int i = 0; i < nb; i++) { int v = sh[i]; sh[i] = acc; acc += v; }
    }
    __syncthreads();
    int i = blockIdx.x * blockDim.x + threadIdx.x;
    if (i < n) {
        // rowptr[i+1] currently = inclusive scan within its 1024-block
        rowptr[i + 1] += sh[i >> 10];
        if (i == 0) rowptr[0] = 0;
    }
}

// ---------------- weight conversion (fp32 -> fp16, zero-padded) ------------
__global__ void k_prep_w(const float* __restrict__ W1, const float* __restrict__ W2,
                         const float* __restrict__ W3, const float* __restrict__ W4,
                         __half* __restrict__ o) {
    int i = blockIdx.x * blockDim.x + threadIdx.x;
    if (i < 6912) {                                    // W1 [88x65] -> [96x72]
        int kk = i / 72;
        int nn = i - kk * 72;
        o[WOFF1 + i] = __float2half((kk < 88 && nn < 65) ? W1[kk * 65 + nn] : 0.f);
    } else if (i < 11392) {                            // W2 [65x50] -> [80x56]
        int j = i - 6912;
        int kk = j / 56;
        int nn = j - kk * 56;
        o[WOFF2 + j] = __float2half((kk < 65 && nn < 50) ? W2[kk * 50 + nn] : 0.f);
    } else if (i < 16000) {                            // W3 [50x65] -> [64x72]
        int j = i - 11392;
        int kk = j / 72;
        int nn = j - kk * 72;
        o[WOFF3 + j] = __float2half((kk < 50 && nn < 65) ? W3[kk * 65 + nn] : 0.f);
    } else if (i < 23040) {                            // W4 [65x88] -> [80x88]
        int j = i - 16000;
        int kk = j / 88;
        int nn = j - kk * 88;
        o[WOFF4 + j] = __float2half((kk < 65 && nn < 88) ? W4[kk * 88 + nn] : 0.f);
    }
}

// ---------------- tensor-core GEMM helpers ---------------------------------
__device__ __forceinline__ void ldsm_x4(unsigned int& a0, unsigned int& a1,
                                        unsigned int& a2, unsigned int& a3,
                                        const __half* p) {
    unsigned int addr = (unsigned int)__cvta_generic_to_shared((const void*)p);
    asm volatile("ldmatrix.sync.aligned.m8n8.x4.shared.b16 {%0,%1,%2,%3}, [%4];"
                 : "=r"(a0), "=r"(a1), "=r"(a2), "=r"(a3)
                 : "r"(addr));
}

__device__ __forceinline__ void ldsm_x2t(unsigned int& b0, unsigned int& b1,
                                         const __half* p) {
    unsigned int addr = (unsigned int)__cvta_generic_to_shared((const void*)p);
    asm volatile("ldmatrix.sync.aligned.m8n8.x2.trans.shared.b16 {%0,%1}, [%2];"
                 : "=r"(b0), "=r"(b1)
                 : "r"(addr));
}

__device__ __forceinline__ void mma16816(float& d0, float& d1, float& d2, float& d3,
                                         unsigned int a0, unsigned int a1,
                                         unsigned int a2, unsigned int a3,
                                         unsigned int b0, unsigned int b1) {
    asm volatile("mma.sync.aligned.m16n8k16.row.col.f32.f16.f16.f32 "
                 "{%0,%1,%2,%3}, {%4,%5,%6,%7}, {%8,%9}, {%0,%1,%2,%3};"
                 : "+f"(d0), "+f"(d1), "+f"(d2), "+f"(d3)
                 : "r"(a0), "r"(a1), "r"(a2), "r"(a3), "r"(b0), "r"(b1));
}

// C[N, Np] = A[N, Kp] * B[Kp, Np] (prepacked fp16 B). 128 rows, 256 threads.
// A-staging uses register prefetch (all LDGs independent -> high MLP).
template <int Kp, int Np, int AF32, int RELU, int SCALE, int OUT_HALF>
__global__ void __launch_bounds__(256)
k_gemm_tc(const void* Av,
          const __half* __restrict__ B,
          const float* __restrict__ bias,
          const float* __restrict__ dinv,
          void* Cv, int ldc, int M, int N) {
    const int KT = Kp / 16;
    const int NT = Np / 8;
    const int LDA = Kp + 8;
    const int LDB = Np;
    extern __shared__ char smem_raw[];
    __half* sA = (__half*)smem_raw;                 // 128 x LDA
    __half* sB = (__half*)smem_raw + 128 * LDA;     // Kp x LDB

    int tid = threadIdx.x;
    int warp = tid >> 5;
    int lane = tid & 31;
    int r0 = blockIdx.x * 128;

    if (AF32) {
        // 128 rows x 22 float4 = 2816 = 11 per thread; prefetch all 11
        const float4* Ag = (const float4*)Av;
        float4 f[11];
#pragma unroll
        for (int it = 0; it < 11; it++) {
            int i = tid + it * 256;
            int r = i / 22;
            int v = i - r * 22;
            int gr = r0 + r;
            f[it] = (gr < N) ? Ag[(size_t)gr * 22 + v]
                             : make_float4(0.f, 0.f, 0.f, 0.f);
        }
#pragma unroll
        for (int it = 0; it < 11; it++) {
            int i = tid + it * 256;
            int r = i / 22;
            int v = i - r * 22;
            __half2* p = (__half2*)&sA[r * LDA + v * 4];
            p[0] = __floats2half2_rn(f[it].x, f[it].y);
            p[1] = __floats2half2_rn(f[it].z, f[it].w);
        }
        for (int i = tid; i < 128 * 4; i += 256) {   // zero cols 88..95
            int r = i >> 2;
            int v = i & 3;
            *(__half2*)&sA[r * LDA + 88 + 2 * v] = __floats2half2_rn(0.f, 0.f);
        }
    } else {
        const int HV = Kp / 8;                       // uint4 per row (10 or 8)
        const int IT = HV / 2;                       // 128*HV/256
        const uint4* Ag = (const uint4*)Av;
        uint4 q[IT];
#pragma unroll
        for (int it = 0; it < IT; it++) {
            int i = tid + it * 256;
            int r = i / HV;
            int v = i - r * HV;
            int gr = r0 + r;
            q[it] = (gr < N) ? Ag[(size_t)gr * HV + v]
                             : make_uint4(0u, 0u, 0u, 0u);
        }
#pragma unroll
        for (int it = 0; it < IT; it++) {
            int i = tid + it * 256;
            int r = i / HV;
            int v = i - r * HV;
            *(uint4*)&sA[r * LDA + v * 8] = q[it];
        }
    }
    {
        const int BV = Np / 8;
        const uint4* Bg = (const uint4*)B;
        for (int i = tid; i < Kp * BV; i += 256) {
            int kk = i / BV;
            int v = i - kk * BV;
            *(uint4*)&sB[kk * LDB + v * 8] = Bg[i];
        }
    }
    __syncthreads();

    float acc[NT][4];
#pragma unroll
    for (int nt = 0; nt < NT; nt++) {
#pragma unroll
        for (int q2 = 0; q2 < 4; q2++) acc[nt][q2] = 0.f;
    }

#pragma unroll
    for (int kt = 0; kt < KT; kt++) {
        unsigned int a0, a1, a2, a3;
        const __half* pa = &sA[(warp * 16 + (lane & 15)) * LDA + kt * 16 + (lane >> 4) * 8];
        ldsm_x4(a0, a1, a2, a3, pa);
#pragma unroll
        for (int nt = 0; nt < NT; nt++) {
            unsigned int b0, b1;
            const __half* pb = &sB[(kt * 16 + (lane & 15)) * LDB + nt * 8];
            ldsm_x2t(b0, b1, pb);
            mma16816(acc[nt][0], acc[nt][1], acc[nt][2], acc[nt][3],
                     a0, a1, a2, a3, b0, b1);
        }
    }

    int row = r0 + warp * 16 + (lane >> 2);
    int colb = (lane & 3) * 2;
    float sc0 = 1.f;
    float sc1 = 1.f;
    if (SCALE) {
        sc0 = (row < N) ? dinv[row] : 0.f;
        sc1 = (row + 8 < N) ? dinv[row + 8] : 0.f;
    }
#pragma unroll
    for (int nt = 0; nt < NT; nt++) {
        int c0 = nt * 8 + colb;
        float b0v = 0.f;
        float b1v = 0.f;
        if (bias != nullptr) {
            b0v = (c0 < M) ? bias[c0] : 0.f;
            b1v = (c0 + 1 < M) ? bias[c0 + 1] : 0.f;
        }
        float v00 = acc[nt][0] + b0v;
        float v01 = acc[nt][1] + b1v;
        float v10 = acc[nt][2] + b0v;
        float v11 = acc[nt][3] + b1v;
        if (RELU) {
            v00 = fmaxf(v00, 0.f); v01 = fmaxf(v01, 0.f);
            v10 = fmaxf(v10, 0.f); v11 = fmaxf(v11, 0.f);
        }
        v00 *= sc0; v01 *= sc0; v10 *= sc1; v11 *= sc1;
        if (c0 >= M)     { v00 = 0.f; v10 = 0.f; }
        if (c0 + 1 >= M) { v01 = 0.f; v11 = 0.f; }
        if (OUT_HALF) {
            __half* C = (__half*)Cv;
            if (row < N)
                *(__half2*)&C[(size_t)row * ldc + c0] = __floats2half2_rn(v00, v01);
            if (row + 8 < N)
                *(__half2*)&C[(size_t)(row + 8) * ldc + c0] = __floats2half2_rn(v10, v11);
        } else {
            float* C = (float*)Cv;
            if (row < N)
                *(float2*)&C[(size_t)row * ldc + c0] = make_float2(v00, v01);
            if (row + 8 < N)
                *(float2*)&C[(size_t)(row + 8) * ldc + c0] = make_float2(v10, v11);
        }
    }
}

// ---------------- aggregation: SUBS edges / gather instruction --------------
// uint4 (8-half) granularity, sector-aligned strides. Warp splits into SUBS
// sub-groups of 32/SUBS lanes; sub-group g gathers edge j+g; shfl reduce.
// 4-deep pipeline (best-known configuration).
__device__ __forceinline__ void add8(float* acc, uint4 q) {
    float2 f;
    f = __half22float2(*(__half2*)&q.x); acc[0] += f.x; acc[1] += f.y;
    f = __half22float2(*(__half2*)&q.y); acc[2] += f.x; acc[3] += f.y;
    f = __half22float2(*(__half2*)&q.z); acc[4] += f.x; acc[5] += f.y;
    f = __half22float2(*(__half2*)&q.w); acc[6] += f.x; acc[7] += f.y;
}

template <int LPE, int SUBS, int SIN, int SOUT, int D>
__global__ void k_agg(const uint4* __restrict__ t, uint4* __restrict__ o,
                      const int* __restrict__ rowptr, const int* __restrict__ csr,
                      const float* __restrict__ dinv,
                      const float* __restrict__ bias,
                      int relu, int post2, int N) {
    const int GRP = 32 / SUBS;          // lanes per sub-group
    int node = (blockIdx.x * blockDim.x + threadIdx.x) >> 5;
    int lane = threadIdx.x & 31;
    if (node >= N) return;
    int sub = lane / GRP;
    int ln = lane & (GRP - 1);
    bool act = ln < LPE;
    int beg = rowptr[node];
    int end = rowptr[node + 1];

    float acc[8];
#pragma unroll
    for (int k = 0; k < 8; k++) acc[k] = 0.f;
    const uint4 z4 = make_uint4(0u, 0u, 0u, 0u);

    int j = beg;
    for (; j + 4 * SUBS <= end; j += 4 * SUBS) {
        int s0 = __ldg(&csr[j + sub]);
        int s1 = __ldg(&csr[j + SUBS + sub]);
        int s2 = __ldg(&csr[j + 2 * SUBS + sub]);
        int s3 = __ldg(&csr[j + 3 * SUBS + sub]);
        uint4 q0 = act ? __ldg(&t[(size_t)s0 * SIN + ln]) : z4;
        uint4 q1 = act ? __ldg(&t[(size_t)s1 * SIN + ln]) : z4;
        uint4 q2 = act ? __ldg(&t[(size_t)s2 * SIN + ln]) : z4;
        uint4 q3 = act ? __ldg(&t[(size_t)s3 * SIN + ln]) : z4;
        add8(acc, q0); add8(acc, q1); add8(acc, q2); add8(acc, q3);
    }
    for (; j + SUBS <= end; j += SUBS) {
        int s0 = __ldg(&csr[j + sub]);
        uint4 q0 = act ? __ldg(&t[(size_t)s0 * SIN + ln]) : z4;
        add8(acc, q0);
    }
    if (j < end) {                        // leftover < SUBS edges
        int rem = end - j;
        uint4 q0 = z4;
        if (act && sub < rem) {
            int s0 = __ldg(&csr[j + sub]);
            q0 = __ldg(&t[(size_t)s0 * SIN + ln]);
        }
        add8(acc, q0);
    }
    // self loop (row already carries dinv_i): sub==0 only
    {
        uint4 q = (act && sub == 0) ? __ldg(&t[(size_t)node * SIN + ln]) : z4;
        add8(acc, q);
    }

    if (SUBS == 4) {
#pragma unroll
        for (int k = 0; k < 8; k++)
            acc[k] += __shfl_xor_sync(0xFFFFFFFFu, acc[k], 8);
    }
#pragma unroll
    for (int k = 0; k < 8; k++)
        acc[k] += __shfl_xor_sync(0xFFFFFFFFu, acc[k], 16);

    if (sub == 0 && ln < SOUT) {
        float di = dinv[node];
        uint4 w;
        __half2* wh2 = (__half2*)&w;
#pragma unroll
        for (int p = 0; p < 4; p++) {
            int c0 = 8 * ln + 2 * p;
            float v0 = acc[2 * p] * di;
            float v1 = acc[2 * p + 1] * di;
            if (bias != nullptr) {
                v0 += (c0 < D) ? bias[c0] : 0.f;
                v1 += (c0 + 1 < D) ? bias[c0 + 1] : 0.f;
            }
            if (relu) { v0 = fmaxf(v0, 0.f); v1 = fmaxf(v1, 0.f); }
            if (post2) { v0 *= di; v1 *= di; }
            if (c0 >= D) v0 = 0.f;
            if (c0 + 1 >= D) v1 = 0.f;
            wh2[p] = __floats2half2_rn(v0, v1);
        }
        o[(size_t)node * SOUT + ln] = w;
    }
}

// ---------------- launch ----------------------------------------------------
extern "C" void kernel_launch(void* const* d_in, const int* in_sizes, int n_in,
                              void* d_out, int out_size) {
    const float* x  = (const float*)d_in[0];
    const float* W1 = (const float*)d_in[1];
    const float* b1 = (const float*)d_in[2];
    const float* W2 = (const float*)d_in[3];
    const float* b2 = (const float*)d_in[4];
    const float* W3 = (const float*)d_in[5];
    const float* b3 = (const float*)d_in[6];
    const float* W4 = (const float*)d_in[7];
    const float* b4 = (const float*)d_in[8];
    const int*   ei = (const int*)d_in[9];

    int N = in_sizes[0] / 88;
    int E = in_sizes[9] / 2;
    const int* src = ei;
    const int* dst = ei + E;
    float* out = (float*)d_out;

    __half *t1, *h1, *t2, *h2, *a3, *t3, *a4, *wh;
    float* dinv;
    int *cnt, *slot, *rowptr, *csr, *bsum;
    cudaGetSymbolAddress((void**)&t1, g_t1);
    cudaGetSymbolAddress((void**)&h1, g_h1);
    cudaGetSymbolAddress((void**)&t2, g_t2);
    cudaGetSymbolAddress((void**)&h2, g_h2);
    cudaGetSymbolAddress((void**)&a3, g_a3);
    cudaGetSymbolAddress((void**)&t3, g_t3);
    cudaGetSymbolAddress((void**)&a4, g_a4);
    cudaGetSymbolAddress((void**)&wh, g_wh);
    cudaGetSymbolAddress((void**)&dinv, g_dinv);
    cudaGetSymbolAddress((void**)&cnt, g_cnt);
    cudaGetSymbolAddress((void**)&slot, g_slot);
    cudaGetSymbolAddress((void**)&rowptr, g_rowptr);
    cudaGetSymbolAddress((void**)&csr, g_csr);
    cudaGetSymbolAddress((void**)&bsum, g_bsum);

    int aggBlocks = (N * 32 + 255) / 256;
    int gemmBlocks = (N + 127) / 128;
    int nb = (N + 1023) / 1024;
    int e4Blocks = ((E + 3) / 4 + 255) / 256;

    const int SM1 = (128 * 104 + 96 * 72) * 2;   // 40448
    const int SM2 = (128 * 88 + 80 * 56) * 2;    // 31488
    const int SM3 = (128 * 72 + 64 * 72) * 2;    // 27648
    const int SM4 = (128 * 88 + 80 * 88) * 2;    // 36608
    cudaFuncSetAttribute(k_gemm_tc<96, 72, 1, 0, 1, 1>,
                         cudaFuncAttributeMaxDynamicSharedMemorySize, SM1);
    cudaFuncSetAttribute(k_gemm_tc<80, 56, 0, 0, 1, 1>,
                         cudaFuncAttributeMaxDynamicSharedMemorySize, SM2);
    cudaFuncSetAttribute(k_gemm_tc<64, 72, 0, 1, 1, 1>,
                         cudaFuncAttributeMaxDynamicSharedMemorySize, SM3);
    cudaFuncSetAttribute(k_gemm_tc<80, 88, 0, 0, 0, 0>,
                         cudaFuncAttributeMaxDynamicSharedMemorySize, SM4);

    cudaMemsetAsync(cnt, 0, (size_t)N * sizeof(int));                 // (memset)
    k_count4<<<e4Blocks, 256>>>(dst, E, cnt, slot);                   // launch 1
    k_scan_block<<<nb, 1024>>>(cnt, N, rowptr + 1, bsum, dinv);       // launch 2
    k_finalize2<<<(N + 255) / 256, 256>>>(bsum, nb, rowptr, N);       // launch 3
    // launch 4 <- profiled slot: ATOMIC-FREE CSR fill
    k_fill4<<<e4Blocks, 256>>>(src, dst, E, rowptr, slot, csr);

    k_prep_w<<<90, 256>>>(W1, W2, W3, W4, wh);                        // launch 5
    // L1: t1 = dinv o (x@W1)
    k_gemm_tc<96, 72, 1, 0, 1, 1><<<gemmBlocks, 256, SM1>>>(
        (const void*)x, wh + WOFF1, nullptr, dinv, (void*)t1, 80, 65, N);

    // L1 agg: h1 = relu(di*S(t1) + b1)
    k_agg<9, 2, 10, 10, 65><<<aggBlocks, 256>>>((const uint4*)t1, (uint4*)h1,
                                                rowptr, csr, dinv, b1, 1, 0, N);
    // L2: t2 = dinv o (h1@W2); h2 = dinv o (di*S(t2) + b2)
    k_gemm_tc<80, 56, 0, 0, 1, 1><<<gemmBlocks, 256, SM2>>>(
        (const void*)h1, wh + WOFF2, nullptr, dinv, (void*)t2, 64, 50, N);
    k_agg<7, 4, 8, 8, 50><<<aggBlocks, 256>>>((const uint4*)t2, (uint4*)h2,
                                              rowptr, csr, dinv, b2, 0, 1, N);
    // L3: a3 = di*S(h2); t3 = dinv o relu(a3@W3 + b3)
    k_agg<7, 4, 8, 8, 50><<<aggBlocks, 256>>>((const uint4*)h2, (uint4*)a3,
                                              rowptr, csr, dinv, nullptr, 0, 0, N);
    k_gemm_tc<64, 72, 0, 1, 1, 1><<<gemmBlocks, 256, SM3>>>(
        (const void*)a3, wh + WOFF3, b3, dinv, (void*)t3, 80, 65, N);
    // L4: a4 = di*S(t3); out = a4@W4 + b4
    k_agg<9, 2, 10, 10, 65><<<aggBlocks, 256>>>((const uint4*)t3, (uint4*)a4,
                                                rowptr, csr, dinv, nullptr, 0, 0, N);
    k_gemm_tc<80, 88, 0, 0, 0, 0><<<gemmBlocks, 256, SM4>>>(
        (const void*)a4, wh + WOFF4, b4, nullptr, (void*)out, 88, 88, N);
}